// round 13
// baseline (speedup 1.0000x reference)
#include <cuda_runtime.h>
#include <cuda_fp16.h>
#include <math.h>
#include <stdint.h>

#define CB 8
#define CS 1024
#define CD 1024
#define CH 16
#define CDK 64
#define CDFF 4096
#define NTOK (CB*CS)
#define CQKV 3072
typedef __half hf;

#define SWZ(o) ((o) ^ (((o) >> 3) & 0x70))
#define CP16(dst, src) asm volatile("cp.async.cg.shared.global [%0], [%1], 16;" :: "r"(dst), "l"(src) : "memory")

#define LDSM4(r, a) \
    asm volatile("ldmatrix.sync.aligned.m8n8.x4.shared.b16 {%0,%1,%2,%3}, [%4];" \
        : "=r"((r)[0]), "=r"((r)[1]), "=r"((r)[2]), "=r"((r)[3]) : "r"(a))
#define LDSM4T(r, a) \
    asm volatile("ldmatrix.sync.aligned.m8n8.x4.trans.shared.b16 {%0,%1,%2,%3}, [%4];" \
        : "=r"((r)[0]), "=r"((r)[1]), "=r"((r)[2]), "=r"((r)[3]) : "r"(a))

#define MMA(c, a, b) \
    asm volatile("mma.sync.aligned.m16n8k16.row.col.f32.f16.f16.f32 " \
        "{%0,%1,%2,%3},{%4,%5,%6,%7},{%8,%9},{%0,%1,%2,%3};" \
        : "+f"((c)[0]), "+f"((c)[1]), "+f"((c)[2]), "+f"((c)[3]) \
        : "r"((a)[0]), "r"((a)[1]), "r"((a)[2]), "r"((a)[3]), "r"((b)[0]), "r"((b)[1]))

__device__ __forceinline__ float gelu_f(float x) {
    float x3 = x * x * x;
    return 0.5f * x * (1.0f + tanhf(0.7978845608028654f * (x + 0.044715f * x3)));
}

// ------------------------- scratch -------------------------
__device__ hf g_xnh[NTOK*CD];
__device__ hf g_qkv[(size_t)NTOK*CQKV];          // [B,S, (Q|K|V) x H*DK]
__device__ hf g_oh[NTOK*CD];
__device__ hf g_h1h[(size_t)NTOK*CDFF];
__device__ hf g_wqkv[(size_t)CQKV*CD];           // rows: wq*0.125 | wk | wv
__device__ float g_bqkv[CQKV];
__device__ hf g_wo[CD*CD];
__device__ hf g_w1[(size_t)CDFF*CD], g_w2[(size_t)CD*CDFF];

__global__ __launch_bounds__(256)
void conv_kernel(const float* __restrict__ w, hf* __restrict__ h, int n4, float scale) {
    int i = blockIdx.x * 256 + threadIdx.x;
    if (i < n4) {
        float4 v = reinterpret_cast<const float4*>(w)[i];
        reinterpret_cast<__half2*>(h)[2*i]   = __floats2half2_rn(v.x * scale, v.y * scale);
        reinterpret_cast<__half2*>(h)[2*i+1] = __floats2half2_rn(v.z * scale, v.w * scale);
    }
}

__global__ __launch_bounds__(256)
void bias_pack_kernel(const float* __restrict__ bq, const float* __restrict__ bk,
                      const float* __restrict__ bv, float* __restrict__ o) {
    int i = blockIdx.x * 256 + threadIdx.x;
    if (i < CD)            o[i] = bq[i] * 0.125f;
    else if (i < 2 * CD)   o[i] = bk[i - CD];
    else if (i < 3 * CD)   o[i] = bv[i - 2 * CD];
}

// ------------------------- LayerNorm: warp-per-row, barrier-free -------------------------
__global__ __launch_bounds__(256)
void ln_kernel(const float* __restrict__ x, const float* __restrict__ gamma,
               const float* __restrict__ beta, hf* __restrict__ oh) {
    const int row = blockIdx.x * 8 + (threadIdx.x >> 5);
    const int lane = threadIdx.x & 31;
    const float4* xr = reinterpret_cast<const float4*>(x + (size_t)row * CD);
    float4 v[8];
#pragma unroll
    for (int i = 0; i < 8; i++) v[i] = xr[lane + 32 * i];

    float s = 0.f;
#pragma unroll
    for (int i = 0; i < 8; i++) s += (v[i].x + v[i].y) + (v[i].z + v[i].w);
#pragma unroll
    for (int o = 16; o > 0; o >>= 1) s += __shfl_xor_sync(~0u, s, o);
    const float mean = s * (1.0f / CD);

    float q = 0.f;
#pragma unroll
    for (int i = 0; i < 8; i++) {
        float a = v[i].x - mean, b = v[i].y - mean;
        float c = v[i].z - mean, d = v[i].w - mean;
        q += (a * a + b * b) + (c * c + d * d);
    }
#pragma unroll
    for (int o = 16; o > 0; o >>= 1) q += __shfl_xor_sync(~0u, q, o);
    const float rstd = 1.0f / (sqrtf(q * (1.0f / (CD - 1))) + 1e-5f);

    const float4* gr = reinterpret_cast<const float4*>(gamma);
    const float4* br = reinterpret_cast<const float4*>(beta);
    hf* orow = oh + (size_t)row * CD;
#pragma unroll
    for (int i = 0; i < 8; i++) {
        float4 g = gr[lane + 32 * i], bb = br[lane + 32 * i];
        __half2 h0 = __floats2half2_rn(g.x * (v[i].x - mean) * rstd + bb.x,
                                       g.y * (v[i].y - mean) * rstd + bb.y);
        __half2 h1 = __floats2half2_rn(g.z * (v[i].z - mean) * rstd + bb.z,
                                       g.w * (v[i].w - mean) * rstd + bb.w);
        uint2 u;
        u.x = *reinterpret_cast<uint32_t*>(&h0);
        u.y = *reinterpret_cast<uint32_t*>(&h1);
        *reinterpret_cast<uint2*>(orow + (lane + 32 * i) * 4) = u;
    }
}

// ---------------------------------------------------------------------------
// Flash attention (R12-proven): O = softmax(mask(Q K^T)) V, Q pre-scaled 0.125.
// ---------------------------------------------------------------------------
__global__ __launch_bounds__(256)
void flash_kernel(const hf* __restrict__ QKV, const int* __restrict__ mask,
                  hf* __restrict__ Oh)
{
    extern __shared__ char smem[];
    const uint32_t sb = (uint32_t)__cvta_generic_to_shared(smem);
    const int tid = threadIdx.x, wid = tid >> 5, lane = tid & 31;
    const int qt = blockIdx.x, z = blockIdx.y;
    const int b = z >> 4, h = z & 15;
    const int qbase = qt * 128;
    const size_t headOff = (size_t)h * 64;

    auto gaddr = [&](int part, int srow, int cu) {
        return QKV + ((size_t)(b * CS + srow) * CQKV + part * CD + headOff + (cu << 3));
    };

#pragma unroll
    for (int i = 0; i < 4; i++) {
        int u = tid + i * 256, r = u >> 3, cu = u & 7;
        CP16(sb + SWZ(r * 128 + cu * 16), gaddr(0, qbase + r, cu));
    }

    auto loadKV = [&](int it, int s) {
        const uint32_t base = sb + 16384 + s * 32768;
        const int kb = it * 128;
#pragma unroll
        for (int i = 0; i < 4; i++) {
            int u = tid + i * 256, r = u >> 3, cu = u & 7;
            uint32_t sw = SWZ(r * 128 + cu * 16);
            CP16(base + sw,         gaddr(1, kb + r, cu));
            CP16(base + 16384 + sw, gaddr(2, kb + r, cu));
        }
    };

    loadKV(0, 0);
    asm volatile("cp.async.commit_group;" ::: "memory");
    loadKV(1, 1);
    asm volatile("cp.async.commit_group;" ::: "memory");

    float oacc[8][4];
#pragma unroll
    for (int i = 0; i < 8; i++)
#pragma unroll
        for (int j = 0; j < 4; j++) oacc[i][j] = 0.f;
    float m_old[2] = {-INFINITY, -INFINITY};
    float l_sum[2] = {0.f, 0.f};

    const int li = lane >> 3, lj = lane & 7;
    const int rbase = wid * 16 + (lane >> 2);

    for (int it = 0; it < 8; it++) {
        const int s = it & 1;
        if (it < 7) asm volatile("cp.async.wait_group 1;" ::: "memory");
        else        asm volatile("cp.async.wait_group 0;" ::: "memory");
        __syncthreads();

        const uint32_t kst = sb + 16384 + s * 32768;
        const uint32_t vst = kst + 16384;

        float sacc[16][4];
#pragma unroll
        for (int i = 0; i < 16; i++)
#pragma unroll
            for (int j = 0; j < 4; j++) sacc[i][j] = 0.f;

#pragma unroll
        for (int kk = 0; kk < 4; kk++) {
            uint32_t ah[4];
            uint32_t aoff = SWZ((wid * 16 + ((li & 1) << 3) + lj) * 128 + (kk * 16 + ((li >> 1) << 3)) * 2);
            LDSM4(ah, sb + aoff);
            uint32_t bh[8][4];
#pragma unroll
            for (int nt = 0; nt < 8; nt++) {
                uint32_t off = SWZ((nt * 16 + ((li >> 1) << 3) + lj) * 128 + (kk * 16 + ((li & 1) << 3)) * 2);
                LDSM4(bh[nt], kst + off);
            }
#pragma unroll
            for (int nt = 0; nt < 8; nt++) { MMA(sacc[2*nt], ah, bh[nt]); MMA(sacc[2*nt+1], ah, bh[nt]+2); }
        }

#pragma unroll
        for (int rr = 0; rr < 2; rr++) {
            const int grow = qbase + rbase + rr * 8;
            const int2* mrow = (const int2*)(mask + ((size_t)(b * CS + grow)) * CS + it * 128 + ((lane & 3) << 1));
            float mx = -INFINITY;
#pragma unroll
            for (int ni = 0; ni < 16; ni++) {
                int2 mv = mrow[ni * 4];
                float v0 = mv.x ? sacc[ni][2*rr]   : -1e9f;
                float v1 = mv.y ? sacc[ni][2*rr+1] : -1e9f;
                sacc[ni][2*rr] = v0; sacc[ni][2*rr+1] = v1;
                mx = fmaxf(mx, fmaxf(v0, v1));
            }
            mx = fmaxf(mx, __shfl_xor_sync(~0u, mx, 1));
            mx = fmaxf(mx, __shfl_xor_sync(~0u, mx, 2));
            const float mnew = fmaxf(m_old[rr], mx);
            const float scl = __expf(m_old[rr] - mnew);
            float rsum = 0.f;
#pragma unroll
            for (int ni = 0; ni < 16; ni++) {
                float p0 = __expf(sacc[ni][2*rr]   - mnew);
                float p1 = __expf(sacc[ni][2*rr+1] - mnew);
                sacc[ni][2*rr] = p0; sacc[ni][2*rr+1] = p1;
                rsum += p0 + p1;
            }
            rsum += __shfl_xor_sync(~0u, rsum, 1);
            rsum += __shfl_xor_sync(~0u, rsum, 2);
            l_sum[rr] = l_sum[rr] * scl + rsum;
            m_old[rr] = mnew;
#pragma unroll
            for (int ni = 0; ni < 8; ni++) { oacc[ni][2*rr] *= scl; oacc[ni][2*rr+1] *= scl; }
        }

#pragma unroll
        for (int kk = 0; kk < 8; kk++) {
            uint32_t ah2[4];
            const int f0 = 2 * kk, f1 = 2 * kk + 1;
            {
                __half2 h0 = __floats2half2_rn(sacc[f0][0], sacc[f0][1]);
                __half2 h1 = __floats2half2_rn(sacc[f0][2], sacc[f0][3]);
                __half2 h2 = __floats2half2_rn(sacc[f1][0], sacc[f1][1]);
                __half2 h3 = __floats2half2_rn(sacc[f1][2], sacc[f1][3]);
                ah2[0] = *reinterpret_cast<uint32_t*>(&h0);
                ah2[1] = *reinterpret_cast<uint32_t*>(&h1);
                ah2[2] = *reinterpret_cast<uint32_t*>(&h2);
                ah2[3] = *reinterpret_cast<uint32_t*>(&h3);
            }
            uint32_t vf[4][4];
#pragma unroll
            for (int nb = 0; nb < 4; nb++) {
                uint32_t off = SWZ((kk * 16 + ((li & 1) << 3) + lj) * 128 + (nb * 16 + ((li >> 1) << 3)) * 2);
                LDSM4T(vf[nb], vst + off);
            }
#pragma unroll
            for (int nb = 0; nb < 4; nb++) { MMA(oacc[2*nb], ah2, vf[nb]); MMA(oacc[2*nb+1], ah2, vf[nb]+2); }
        }

        __syncthreads();
        if (it + 2 < 8) {
            loadKV(it + 2, s);
            asm volatile("cp.async.commit_group;" ::: "memory");
        }
    }

#pragma unroll
    for (int rr = 0; rr < 2; rr++) {
        const int grow = qbase + rbase + rr * 8;
        const float inv = 1.f / l_sum[rr];
        const size_t base = (size_t)(b * CS + grow) * CD + headOff + ((lane & 3) << 1);
#pragma unroll
        for (int ni = 0; ni < 8; ni++) {
            float v0 = oacc[ni][2*rr] * inv, v1 = oacc[ni][2*rr+1] * inv;
            *reinterpret_cast<__half2*>(&Oh[base + 8 * ni]) = __floats2half2_rn(v0, v1);
        }
    }
}

// ---------------------------------------------------------------------------
// mma.sync fp16 GEMM, CUTLASS-sm80 style: 128x128 CTA, 4 warps, warp 64x64.
// 3-stage cp.async + register fragment double-buffer. K = NC*64.
// ---------------------------------------------------------------------------
__global__ __launch_bounds__(128, 2)
void mm_gemm(const hf* __restrict__ Ah, int lda,
             const hf* __restrict__ Bh, int ldb,
             float* __restrict__ outf, hf* __restrict__ outh, int ldc,
             const float* __restrict__ bias, const float* __restrict__ res,
             int gelu, int NC)
{
    constexpr int ASZ = 128 * 128;          // 16 KB
    constexpr int STG = 2 * ASZ;            // 32 KB / stage

    extern __shared__ char smem[];
    const uint32_t sb = (uint32_t)__cvta_generic_to_shared(smem);
    const int tid = threadIdx.x, wid = tid >> 5, lane = tid & 31;
    const int bm = blockIdx.y * 128, bn = blockIdx.x * 128;

    const int wm = (wid & 1) * 64;
    const int wn = (wid >> 1) * 64;

    auto load_chunk = [&](int c, int s) {
        const uint32_t base = sb + s * STG;
        const int k0 = c * 64;
#pragma unroll
        for (int i = 0; i < 8; i++) {
            int u = tid + i * 128, r = u >> 3, cu = u & 7;
            CP16(base + SWZ(r * 128 + cu * 16), Ah + (size_t)(bm + r) * lda + k0 + cu * 8);
        }
#pragma unroll
        for (int i = 0; i < 8; i++) {
            int u = tid + i * 128, r = u >> 3, cu = u & 7;
            CP16(base + ASZ + SWZ(r * 128 + cu * 16), Bh + (size_t)(bn + r) * ldb + k0 + cu * 8);
        }
    };

    float acc[4][8][4];
#pragma unroll
    for (int mi = 0; mi < 4; mi++)
#pragma unroll
        for (int ni = 0; ni < 8; ni++)
#pragma unroll
            for (int cc = 0; cc < 4; cc++) acc[mi][ni][cc] = 0.f;

    load_chunk(0, 0);
    asm volatile("cp.async.commit_group;" ::: "memory");
    load_chunk(1, 1);
    asm volatile("cp.async.commit_group;" ::: "memory");

    const int li = lane >> 3, lj = lane & 7;

    uint32_t af[2][4][4];
    uint32_t bf[2][8][2];

    for (int c = 0; c < NC; c++) {
        if (c + 2 < NC) {
            load_chunk(c + 2, (c + 2) % 3);
            asm volatile("cp.async.commit_group;" ::: "memory");
            asm volatile("cp.async.wait_group 2;" ::: "memory");
        } else if (c + 1 < NC) {
            asm volatile("cp.async.wait_group 1;" ::: "memory");
        } else {
            asm volatile("cp.async.wait_group 0;" ::: "memory");
        }
        __syncthreads();

        const uint32_t aBase = sb + (c % 3) * STG;
        const uint32_t bBase = aBase + ASZ;

        auto ld_frags = [&](int ks, uint32_t a[4][4], uint32_t b[8][2]) {
            const int kb = ks * 16;
#pragma unroll
            for (int mi = 0; mi < 4; mi++) {
                int row = wm + mi * 16 + ((li & 1) << 3) + lj;
                int col = kb + ((li >> 1) << 3);
                LDSM4(a[mi], aBase + SWZ(row * 128 + col * 2));
            }
#pragma unroll
            for (int nt = 0; nt < 4; nt++) {
                int row = wn + nt * 16 + ((li >> 1) << 3) + lj;
                int col = kb + ((li & 1) << 3);
                uint32_t r4[4];
                LDSM4(r4, bBase + SWZ(row * 128 + col * 2));
                b[2*nt][0] = r4[0];   b[2*nt][1] = r4[1];
                b[2*nt+1][0] = r4[2]; b[2*nt+1][1] = r4[3];
            }
        };

        ld_frags(0, af[0], bf[0]);
#pragma unroll
        for (int ks = 0; ks < 4; ks++) {
            const int cur = ks & 1;
            if (ks < 3) ld_frags(ks + 1, af[cur ^ 1], bf[cur ^ 1]);
#pragma unroll
            for (int mi = 0; mi < 4; mi++)
#pragma unroll
                for (int ni = 0; ni < 8; ni++)
                    MMA(acc[mi][ni], af[cur][mi], bf[cur][ni]);
        }
        __syncthreads();
    }

#pragma unroll
    for (int mi = 0; mi < 4; mi++) {
#pragma unroll
        for (int ni = 0; ni < 8; ni++) {
            const int m0 = bm + wm + mi * 16 + (lane >> 2);
            const int n0 = bn + wn + ni * 8 + ((lane & 3) << 1);
#pragma unroll
            for (int rr = 0; rr < 2; rr++) {
                const int m = m0 + rr * 8;
                float v0 = acc[mi][ni][2*rr + 0];
                float v1 = acc[mi][ni][2*rr + 1];
                if (bias) { v0 += bias[n0]; v1 += bias[n0 + 1]; }
                if (gelu) { v0 = gelu_f(v0); v1 = gelu_f(v1); }
                size_t idx = (size_t)m * ldc + n0;
                if (res) { v0 += res[idx]; v1 += res[idx + 1]; }
                if (outf) {
                    outf[idx] = v0; outf[idx + 1] = v1;
                } else {
                    *reinterpret_cast<__half2*>(&outh[idx]) = __floats2half2_rn(v0, v1);
                }
            }
        }
    }
}

// ---------------------------------------------------------------------------
extern "C" void kernel_launch(void* const* d_in, const int* in_sizes, int n_in,
                              void* d_out, int out_size)
{
    const float* x    = (const float*)d_in[0];
    const int*   mask = (const int*)  d_in[1];
    const float* wq = (const float*)d_in[2],  *bq = (const float*)d_in[3];
    const float* wk = (const float*)d_in[4],  *bk = (const float*)d_in[5];
    const float* wv = (const float*)d_in[6],  *bv = (const float*)d_in[7];
    const float* wo = (const float*)d_in[8],  *bo = (const float*)d_in[9];
    const float* w1 = (const float*)d_in[10], *b1 = (const float*)d_in[11];
    const float* w2 = (const float*)d_in[12], *b2 = (const float*)d_in[13];
    const float* g1 = (const float*)d_in[14], *be1 = (const float*)d_in[15];
    const float* g2 = (const float*)d_in[16], *be2 = (const float*)d_in[17];
    float* out = (float*)d_out;

    hf *xnh,*qkv,*oh,*h1h,*wqkvc,*woc,*w1c,*w2c;
    float *bqkv;
    cudaGetSymbolAddress((void**)&xnh, g_xnh);
    cudaGetSymbolAddress((void**)&qkv, g_qkv);
    cudaGetSymbolAddress((void**)&oh, g_oh);
    cudaGetSymbolAddress((void**)&h1h, g_h1h);
    cudaGetSymbolAddress((void**)&wqkvc, g_wqkv);
    cudaGetSymbolAddress((void**)&bqkv, g_bqkv);
    cudaGetSymbolAddress((void**)&woc, g_wo);
    cudaGetSymbolAddress((void**)&w1c, g_w1);
    cudaGetSymbolAddress((void**)&w2c, g_w2);

    const int SMGM = 3 * 32768;              // 98304, 3-stage 128x128
    const int SMFL = 16384 + 2 * 32768;      // 81920
    cudaFuncSetAttribute((const void*)mm_gemm, cudaFuncAttributeMaxDynamicSharedMemorySize, SMGM);
    cudaFuncSetAttribute((const void*)flash_kernel, cudaFuncAttributeMaxDynamicSharedMemorySize, SMFL);

    // pack weights: wq*0.125 | wk | wv into g_wqkv; bias packed likewise
    conv_kernel<<<1024, 256>>>(wq, wqkvc,               CD * CD / 4, 0.125f);
    conv_kernel<<<1024, 256>>>(wk, wqkvc + CD * CD,     CD * CD / 4, 1.0f);
    conv_kernel<<<1024, 256>>>(wv, wqkvc + 2 * CD * CD, CD * CD / 4, 1.0f);
    bias_pack_kernel<<<12, 256>>>(bq, bk, bv, bqkv);
    conv_kernel<<<1024, 256>>>(wo, woc, CD * CD / 4, 1.0f);
    conv_kernel<<<4096, 256>>>(w1, w1c, CDFF * CD / 4, 1.0f);
    conv_kernel<<<4096, 256>>>(w2, w2c, CD * CDFF / 4, 1.0f);

    // LN1 -> xn (fp16), warp-per-row
    ln_kernel<<<NTOK / 8, 256>>>(x, g1, be1, xnh);

    // fused QKV projection -> [B,S,3072] (Q pre-scaled by 0.125)
    mm_gemm<<<dim3(CQKV / 128, NTOK / 128), 128, SMGM>>>(
        xnh, CD, wqkvc, CD, nullptr, qkv, CQKV, bqkv, nullptr, 0, 16);

    // fused attention -> O (fp16)
    dim3 gA(CS / 128, CB * CH);
    flash_kernel<<<gA, 256, SMFL>>>(qkv, mask, oh);

    // x1 = O wo^T + bo + x -> out (fp32)
    mm_gemm<<<dim3(CD / 128, NTOK / 128), 128, SMGM>>>(
        oh, CD, woc, CD, out, nullptr, CD, bo, x, 0, 16);

    // LN2 -> xn (fp16), warp-per-row
    ln_kernel<<<NTOK / 8, 256>>>(out, g2, be2, xnh);

    // h1 = gelu(xn w1^T + b1) (fp16)
    mm_gemm<<<dim3(CDFF / 128, NTOK / 128), 128, SMGM>>>(
        xnh, CD, w1c, CD, nullptr, h1h, CDFF, b1, nullptr, 1, 16);

    // out = x1 + h1 w2^T + b2
    mm_gemm<<<dim3(CD / 128, NTOK / 128), 128, SMGM>>>(
        h1h, CDFF, w2c, CDFF, out, nullptr, CD, b2, out, 0, 64);
}

// round 14
// speedup vs baseline: 1.0148x; 1.0148x over previous
#include <cuda_runtime.h>
#include <cuda_fp16.h>
#include <math.h>
#include <stdint.h>

#define CB 8
#define CS 1024
#define CD 1024
#define CH 16
#define CDK 64
#define CDFF 4096
#define NTOK (CB*CS)
#define CQKV 3072
typedef __half hf;

#define SWZ(o) ((o) ^ (((o) >> 3) & 0x70))
#define CP16(dst, src) asm volatile("cp.async.cg.shared.global [%0], [%1], 16;" :: "r"(dst), "l"(src) : "memory")

#define LDSM4(r, a) \
    asm volatile("ldmatrix.sync.aligned.m8n8.x4.shared.b16 {%0,%1,%2,%3}, [%4];" \
        : "=r"((r)[0]), "=r"((r)[1]), "=r"((r)[2]), "=r"((r)[3]) : "r"(a))
#define LDSM4T(r, a) \
    asm volatile("ldmatrix.sync.aligned.m8n8.x4.trans.shared.b16 {%0,%1,%2,%3}, [%4];" \
        : "=r"((r)[0]), "=r"((r)[1]), "=r"((r)[2]), "=r"((r)[3]) : "r"(a))

#define MMA(c, a, b) \
    asm volatile("mma.sync.aligned.m16n8k16.row.col.f32.f16.f16.f32 " \
        "{%0,%1,%2,%3},{%4,%5,%6,%7},{%8,%9},{%0,%1,%2,%3};" \
        : "+f"((c)[0]), "+f"((c)[1]), "+f"((c)[2]), "+f"((c)[3]) \
        : "r"((a)[0]), "r"((a)[1]), "r"((a)[2]), "r"((a)[3]), "r"((b)[0]), "r"((b)[1]))

__device__ __forceinline__ float gelu_f(float x) {
    float x3 = x * x * x;
    return 0.5f * x * (1.0f + tanhf(0.7978845608028654f * (x + 0.044715f * x3)));
}

// ------------------------- scratch -------------------------
__device__ hf g_xnh[NTOK*CD];
__device__ hf g_qkv[(size_t)NTOK*CQKV];          // [B,S, (Q|K|V) x H*DK]
__device__ hf g_oh[NTOK*CD];
__device__ hf g_h1h[(size_t)NTOK*CDFF];
__device__ hf g_wqkv[(size_t)CQKV*CD];           // rows: wq*0.125 | wk | wv
__device__ float g_bqkv[CQKV];
__device__ hf g_wo[CD*CD];
__device__ hf g_w1[(size_t)CDFF*CD], g_w2[(size_t)CD*CDFF];

__global__ __launch_bounds__(256)
void conv_kernel(const float* __restrict__ w, hf* __restrict__ h, int n4, float scale) {
    int i = blockIdx.x * 256 + threadIdx.x;
    if (i < n4) {
        float4 v = reinterpret_cast<const float4*>(w)[i];
        reinterpret_cast<__half2*>(h)[2*i]   = __floats2half2_rn(v.x * scale, v.y * scale);
        reinterpret_cast<__half2*>(h)[2*i+1] = __floats2half2_rn(v.z * scale, v.w * scale);
    }
}

__global__ __launch_bounds__(256)
void bias_pack_kernel(const float* __restrict__ bq, const float* __restrict__ bk,
                      const float* __restrict__ bv, float* __restrict__ o) {
    int i = blockIdx.x * 256 + threadIdx.x;
    if (i < CD)            o[i] = bq[i] * 0.125f;
    else if (i < 2 * CD)   o[i] = bk[i - CD];
    else if (i < 3 * CD)   o[i] = bv[i - 2 * CD];
}

// ------------------------- LayerNorm: warp-per-row, barrier-free -------------------------
__global__ __launch_bounds__(256)
void ln_kernel(const float* __restrict__ x, const float* __restrict__ gamma,
               const float* __restrict__ beta, hf* __restrict__ oh) {
    const int row = blockIdx.x * 8 + (threadIdx.x >> 5);
    const int lane = threadIdx.x & 31;
    const float4* xr = reinterpret_cast<const float4*>(x + (size_t)row * CD);
    float4 v[8];
#pragma unroll
    for (int i = 0; i < 8; i++) v[i] = xr[lane + 32 * i];

    float s = 0.f;
#pragma unroll
    for (int i = 0; i < 8; i++) s += (v[i].x + v[i].y) + (v[i].z + v[i].w);
#pragma unroll
    for (int o = 16; o > 0; o >>= 1) s += __shfl_xor_sync(~0u, s, o);
    const float mean = s * (1.0f / CD);

    float q = 0.f;
#pragma unroll
    for (int i = 0; i < 8; i++) {
        float a = v[i].x - mean, b = v[i].y - mean;
        float c = v[i].z - mean, d = v[i].w - mean;
        q += (a * a + b * b) + (c * c + d * d);
    }
#pragma unroll
    for (int o = 16; o > 0; o >>= 1) q += __shfl_xor_sync(~0u, q, o);
    const float rstd = 1.0f / (sqrtf(q * (1.0f / (CD - 1))) + 1e-5f);

    const float4* gr = reinterpret_cast<const float4*>(gamma);
    const float4* br = reinterpret_cast<const float4*>(beta);
    hf* orow = oh + (size_t)row * CD;
#pragma unroll
    for (int i = 0; i < 8; i++) {
        float4 g = gr[lane + 32 * i], bb = br[lane + 32 * i];
        __half2 h0 = __floats2half2_rn(g.x * (v[i].x - mean) * rstd + bb.x,
                                       g.y * (v[i].y - mean) * rstd + bb.y);
        __half2 h1 = __floats2half2_rn(g.z * (v[i].z - mean) * rstd + bb.z,
                                       g.w * (v[i].w - mean) * rstd + bb.w);
        uint2 u;
        u.x = *reinterpret_cast<uint32_t*>(&h0);
        u.y = *reinterpret_cast<uint32_t*>(&h1);
        *reinterpret_cast<uint2*>(orow + (lane + 32 * i) * 4) = u;
    }
}

// ---------------------------------------------------------------------------
// Flash attention: O = softmax(mask(Q K^T)) V with Q pre-scaled by 0.125.
// ---------------------------------------------------------------------------
__global__ __launch_bounds__(256)
void flash_kernel(const hf* __restrict__ QKV, const int* __restrict__ mask,
                  hf* __restrict__ Oh)
{
    extern __shared__ char smem[];
    const uint32_t sb = (uint32_t)__cvta_generic_to_shared(smem);
    const int tid = threadIdx.x, wid = tid >> 5, lane = tid & 31;
    const int qt = blockIdx.x, z = blockIdx.y;
    const int b = z >> 4, h = z & 15;
    const int qbase = qt * 128;
    const size_t headOff = (size_t)h * 64;

    auto gaddr = [&](int part, int srow, int cu) {
        return QKV + ((size_t)(b * CS + srow) * CQKV + part * CD + headOff + (cu << 3));
    };

#pragma unroll
    for (int i = 0; i < 4; i++) {
        int u = tid + i * 256, r = u >> 3, cu = u & 7;
        CP16(sb + SWZ(r * 128 + cu * 16), gaddr(0, qbase + r, cu));
    }

    auto loadKV = [&](int it, int s) {
        const uint32_t base = sb + 16384 + s * 32768;
        const int kb = it * 128;
#pragma unroll
        for (int i = 0; i < 4; i++) {
            int u = tid + i * 256, r = u >> 3, cu = u & 7;
            uint32_t sw = SWZ(r * 128 + cu * 16);
            CP16(base + sw,         gaddr(1, kb + r, cu));
            CP16(base + 16384 + sw, gaddr(2, kb + r, cu));
        }
    };

    loadKV(0, 0);
    asm volatile("cp.async.commit_group;" ::: "memory");
    loadKV(1, 1);
    asm volatile("cp.async.commit_group;" ::: "memory");

    float oacc[8][4];
#pragma unroll
    for (int i = 0; i < 8; i++)
#pragma unroll
        for (int j = 0; j < 4; j++) oacc[i][j] = 0.f;
    float m_old[2] = {-INFINITY, -INFINITY};
    float l_sum[2] = {0.f, 0.f};

    const int li = lane >> 3, lj = lane & 7;
    const int rbase = wid * 16 + (lane >> 2);

    for (int it = 0; it < 8; it++) {
        const int s = it & 1;
        if (it < 7) asm volatile("cp.async.wait_group 1;" ::: "memory");
        else        asm volatile("cp.async.wait_group 0;" ::: "memory");
        __syncthreads();

        const uint32_t kst = sb + 16384 + s * 32768;
        const uint32_t vst = kst + 16384;

        float sacc[16][4];
#pragma unroll
        for (int i = 0; i < 16; i++)
#pragma unroll
            for (int j = 0; j < 4; j++) sacc[i][j] = 0.f;

#pragma unroll
        for (int kk = 0; kk < 4; kk++) {
            uint32_t ah[4];
            uint32_t aoff = SWZ((wid * 16 + ((li & 1) << 3) + lj) * 128 + (kk * 16 + ((li >> 1) << 3)) * 2);
            LDSM4(ah, sb + aoff);
            uint32_t bh[8][4];
#pragma unroll
            for (int nt = 0; nt < 8; nt++) {
                uint32_t off = SWZ((nt * 16 + ((li >> 1) << 3) + lj) * 128 + (kk * 16 + ((li & 1) << 3)) * 2);
                LDSM4(bh[nt], kst + off);
            }
#pragma unroll
            for (int nt = 0; nt < 8; nt++) { MMA(sacc[2*nt], ah, bh[nt]); MMA(sacc[2*nt+1], ah, bh[nt]+2); }
        }

#pragma unroll
        for (int rr = 0; rr < 2; rr++) {
            const int grow = qbase + rbase + rr * 8;
            const int2* mrow = (const int2*)(mask + ((size_t)(b * CS + grow)) * CS + it * 128 + ((lane & 3) << 1));
            float mx = -INFINITY;
#pragma unroll
            for (int ni = 0; ni < 16; ni++) {
                int2 mv = mrow[ni * 4];
                float v0 = mv.x ? sacc[ni][2*rr]   : -1e9f;
                float v1 = mv.y ? sacc[ni][2*rr+1] : -1e9f;
                sacc[ni][2*rr] = v0; sacc[ni][2*rr+1] = v1;
                mx = fmaxf(mx, fmaxf(v0, v1));
            }
            mx = fmaxf(mx, __shfl_xor_sync(~0u, mx, 1));
            mx = fmaxf(mx, __shfl_xor_sync(~0u, mx, 2));
            const float mnew = fmaxf(m_old[rr], mx);
            const float scl = __expf(m_old[rr] - mnew);
            float rsum = 0.f;
#pragma unroll
            for (int ni = 0; ni < 16; ni++) {
                float p0 = __expf(sacc[ni][2*rr]   - mnew);
                float p1 = __expf(sacc[ni][2*rr+1] - mnew);
                sacc[ni][2*rr] = p0; sacc[ni][2*rr+1] = p1;
                rsum += p0 + p1;
            }
            rsum += __shfl_xor_sync(~0u, rsum, 1);
            rsum += __shfl_xor_sync(~0u, rsum, 2);
            l_sum[rr] = l_sum[rr] * scl + rsum;
            m_old[rr] = mnew;
#pragma unroll
            for (int ni = 0; ni < 8; ni++) { oacc[ni][2*rr] *= scl; oacc[ni][2*rr+1] *= scl; }
        }

#pragma unroll
        for (int kk = 0; kk < 8; kk++) {
            uint32_t ah2[4];
            const int f0 = 2 * kk, f1 = 2 * kk + 1;
            {
                __half2 h0 = __floats2half2_rn(sacc[f0][0], sacc[f0][1]);
                __half2 h1 = __floats2half2_rn(sacc[f0][2], sacc[f0][3]);
                __half2 h2 = __floats2half2_rn(sacc[f1][0], sacc[f1][1]);
                __half2 h3 = __floats2half2_rn(sacc[f1][2], sacc[f1][3]);
                ah2[0] = *reinterpret_cast<uint32_t*>(&h0);
                ah2[1] = *reinterpret_cast<uint32_t*>(&h1);
                ah2[2] = *reinterpret_cast<uint32_t*>(&h2);
                ah2[3] = *reinterpret_cast<uint32_t*>(&h3);
            }
            uint32_t vf[4][4];
#pragma unroll
            for (int nb = 0; nb < 4; nb++) {
                uint32_t off = SWZ((kk * 16 + ((li & 1) << 3) + lj) * 128 + (nb * 16 + ((li >> 1) << 3)) * 2);
                LDSM4T(vf[nb], vst + off);
            }
#pragma unroll
            for (int nb = 0; nb < 4; nb++) { MMA(oacc[2*nb], ah2, vf[nb]); MMA(oacc[2*nb+1], ah2, vf[nb]+2); }
        }

        __syncthreads();
        if (it + 2 < 8) {
            loadKV(it + 2, s);
            asm volatile("cp.async.commit_group;" ::: "memory");
        }
    }

#pragma unroll
    for (int rr = 0; rr < 2; rr++) {
        const int grow = qbase + rbase + rr * 8;
        const float inv = 1.f / l_sum[rr];
        const size_t base = (size_t)(b * CS + grow) * CD + headOff + ((lane & 3) << 1);
#pragma unroll
        for (int ni = 0; ni < 8; ni++) {
            float v0 = oacc[ni][2*rr] * inv, v1 = oacc[ni][2*rr+1] * inv;
            *reinterpret_cast<__half2*>(&Oh[base + 8 * ni]) = __floats2half2_rn(v0, v1);
        }
    }
}

// ---------------------------------------------------------------------------
// mma.sync fp16 GEMM (1-pass, 3-stage pipeline): C[BM x BN] = A . B^T, K=NC*64.
// Warp tile fixed 32x64 (NF=8); warp grid (BM/32) x (BN/64).
// ---------------------------------------------------------------------------
template<int BM, int BN>
__global__ __launch_bounds__((BM/32)*(BN/64)*32)
void mm_gemm(const hf* __restrict__ Ah, int lda,
             const hf* __restrict__ Bh, int ldb,
             float* __restrict__ outf, hf* __restrict__ outh, int ldc,
             const float* __restrict__ bias, const float* __restrict__ res,
             int gelu, int NC)
{
    constexpr int WMC = BM / 32;
    constexpr int WNC = BN / 64;
    constexpr int THREADS = WMC * WNC * 32;
    constexpr int NF  = 8;
    constexpr int ASZ = BM * 128;
    constexpr int BSZ = BN * 128;
    constexpr int STG = ASZ + BSZ;

    extern __shared__ char smem[];
    const uint32_t sb = (uint32_t)__cvta_generic_to_shared(smem);
    const int tid = threadIdx.x, wid = tid >> 5, lane = tid & 31;
    const int bm = blockIdx.y * BM, bn = blockIdx.x * BN;

    const int wm = (wid % WMC) * 32;
    const int wn = (wid / WMC) * 64;

    auto load_chunk = [&](int c, int s) {
        const uint32_t base = sb + s * STG;
        const int k0 = c * 64;
#pragma unroll
        for (int i = 0; i < BM * 8 / THREADS; i++) {
            int u = tid + i * THREADS, r = u >> 3, cu = u & 7;
            CP16(base + SWZ(r * 128 + cu * 16), Ah + (size_t)(bm + r) * lda + k0 + cu * 8);
        }
#pragma unroll
        for (int i = 0; i < BN * 8 / THREADS; i++) {
            int u = tid + i * THREADS, r = u >> 3, cu = u & 7;
            CP16(base + ASZ + SWZ(r * 128 + cu * 16), Bh + (size_t)(bn + r) * ldb + k0 + cu * 8);
        }
    };

    float acc[2][NF][4];
#pragma unroll
    for (int mi = 0; mi < 2; mi++)
#pragma unroll
        for (int ni = 0; ni < NF; ni++)
#pragma unroll
            for (int cc = 0; cc < 4; cc++) acc[mi][ni][cc] = 0.f;

    load_chunk(0, 0);
    asm volatile("cp.async.commit_group;" ::: "memory");
    load_chunk(1, 1);
    asm volatile("cp.async.commit_group;" ::: "memory");

    const int li = lane >> 3, lj = lane & 7;

    for (int c = 0; c < NC; c++) {
        if (c + 2 < NC) {
            load_chunk(c + 2, (c + 2) % 3);
            asm volatile("cp.async.commit_group;" ::: "memory");
            asm volatile("cp.async.wait_group 2;" ::: "memory");
        } else if (c + 1 < NC) {
            asm volatile("cp.async.wait_group 1;" ::: "memory");
        } else {
            asm volatile("cp.async.wait_group 0;" ::: "memory");
        }
        __syncthreads();

        const uint32_t aBase = sb + (c % 3) * STG;
        const uint32_t bBase = aBase + ASZ;

#pragma unroll
        for (int ks = 0; ks < 4; ks++) {
            const int kb = ks * 16;
            uint32_t ah[2][4];
#pragma unroll
            for (int mi = 0; mi < 2; mi++) {
                int row = wm + mi * 16 + ((li & 1) << 3) + lj;
                int col = kb + ((li >> 1) << 3);
                LDSM4(ah[mi], aBase + SWZ(row * 128 + col * 2));
            }
            uint32_t bh[NF][2];
#pragma unroll
            for (int nt = 0; nt < NF / 2; nt++) {
                int row = wn + nt * 16 + ((li >> 1) << 3) + lj;
                int col = kb + ((li & 1) << 3);
                uint32_t r4[4];
                LDSM4(r4, bBase + SWZ(row * 128 + col * 2));
                bh[2*nt][0] = r4[0]; bh[2*nt][1] = r4[1];
                bh[2*nt+1][0] = r4[2]; bh[2*nt+1][1] = r4[3];
            }
#pragma unroll
            for (int mi = 0; mi < 2; mi++)
#pragma unroll
                for (int ni = 0; ni < NF; ni++) MMA(acc[mi][ni], ah[mi], bh[ni]);
        }
        __syncthreads();
    }

#pragma unroll
    for (int mi = 0; mi < 2; mi++) {
#pragma unroll
        for (int ni = 0; ni < NF; ni++) {
            const int m0 = bm + wm + mi * 16 + (lane >> 2);
            const int n0 = bn + wn + ni * 8 + ((lane & 3) << 1);
#pragma unroll
            for (int rr = 0; rr < 2; rr++) {
                const int m = m0 + rr * 8;
                float v0 = acc[mi][ni][2*rr + 0];
                float v1 = acc[mi][ni][2*rr + 1];
                if (bias) { v0 += bias[n0]; v1 += bias[n0 + 1]; }
                if (gelu) { v0 = gelu_f(v0); v1 = gelu_f(v1); }
                size_t idx = (size_t)m * ldc + n0;
                if (res) { v0 += res[idx]; v1 += res[idx + 1]; }
                if (outf) {
                    outf[idx] = v0; outf[idx + 1] = v1;
                } else {
                    *reinterpret_cast<__half2*>(&outh[idx]) = __floats2half2_rn(v0, v1);
                }
            }
        }
    }
}

// ---------------------------------------------------------------------------
extern "C" void kernel_launch(void* const* d_in, const int* in_sizes, int n_in,
                              void* d_out, int out_size)
{
    const float* x    = (const float*)d_in[0];
    const int*   mask = (const int*)  d_in[1];
    const float* wq = (const float*)d_in[2],  *bq = (const float*)d_in[3];
    const float* wk = (const float*)d_in[4],  *bk = (const float*)d_in[5];
    const float* wv = (const float*)d_in[6],  *bv = (const float*)d_in[7];
    const float* wo = (const float*)d_in[8],  *bo = (const float*)d_in[9];
    const float* w1 = (const float*)d_in[10], *b1 = (const float*)d_in[11];
    const float* w2 = (const float*)d_in[12], *b2 = (const float*)d_in[13];
    const float* g1 = (const float*)d_in[14], *be1 = (const float*)d_in[15];
    const float* g2 = (const float*)d_in[16], *be2 = (const float*)d_in[17];
    float* out = (float*)d_out;

    hf *xnh,*qkv,*oh,*h1h,*wqkvc,*woc,*w1c,*w2c;
    float *bqkv;
    cudaGetSymbolAddress((void**)&xnh, g_xnh);
    cudaGetSymbolAddress((void**)&qkv, g_qkv);
    cudaGetSymbolAddress((void**)&oh, g_oh);
    cudaGetSymbolAddress((void**)&h1h, g_h1h);
    cudaGetSymbolAddress((void**)&wqkvc, g_wqkv);
    cudaGetSymbolAddress((void**)&bqkv, g_bqkv);
    cudaGetSymbolAddress((void**)&woc, g_wo);
    cudaGetSymbolAddress((void**)&w1c, g_w1);
    cudaGetSymbolAddress((void**)&w2c, g_w2);

    const int SMBIG = 3 * (128 + 256) * 128;     // 147456
    const int SMSML = 3 * (64 + 128) * 128;      // 73728
    const int SMFL  = 16384 + 2 * 32768;         // 81920
    cudaFuncSetAttribute((const void*)mm_gemm<128,256>, cudaFuncAttributeMaxDynamicSharedMemorySize, SMBIG);
    cudaFuncSetAttribute((const void*)mm_gemm<64,128>,  cudaFuncAttributeMaxDynamicSharedMemorySize, SMSML);
    cudaFuncSetAttribute((const void*)flash_kernel, cudaFuncAttributeMaxDynamicSharedMemorySize, SMFL);

    // Side stream for weight packing, joined into the capture via events.
    // Created fresh each call (kernel_launch runs only a few times; no device
    // allocations involved) so every call performs identical work.
    cudaStream_t s1;
    cudaEvent_t eF, eW1, eW2;
    cudaStreamCreateWithFlags(&s1, cudaStreamNonBlocking);
    cudaEventCreateWithFlags(&eF,  cudaEventDisableTiming);
    cudaEventCreateWithFlags(&eW1, cudaEventDisableTiming);
    cudaEventCreateWithFlags(&eW2, cudaEventDisableTiming);

    // fork
    cudaEventRecord(eF, 0);
    cudaStreamWaitEvent(s1, eF, 0);

    // side stream: QKV weights first (needed soonest), then wo/w1/w2
    conv_kernel<<<1024, 256, 0, s1>>>(wq, wqkvc,               CD * CD / 4, 0.125f);
    conv_kernel<<<1024, 256, 0, s1>>>(wk, wqkvc + CD * CD,     CD * CD / 4, 1.0f);
    conv_kernel<<<1024, 256, 0, s1>>>(wv, wqkvc + 2 * CD * CD, CD * CD / 4, 1.0f);
    bias_pack_kernel<<<12, 256, 0, s1>>>(bq, bk, bv, bqkv);
    cudaEventRecord(eW1, s1);
    conv_kernel<<<1024, 256, 0, s1>>>(wo, woc, CD * CD / 4, 1.0f);
    conv_kernel<<<4096, 256, 0, s1>>>(w1, w1c, CDFF * CD / 4, 1.0f);
    conv_kernel<<<4096, 256, 0, s1>>>(w2, w2c, CD * CDFF / 4, 1.0f);
    cudaEventRecord(eW2, s1);

    // main stream: LN1 overlaps QKV weight conversion
    ln_kernel<<<NTOK / 8, 256>>>(x, g1, be1, xnh);

    // join 1: QKV weights ready
    cudaStreamWaitEvent(0, eW1, 0);
    mm_gemm<128,256><<<dim3(CQKV / 256, NTOK / 128), 512, SMBIG>>>(
        xnh, CD, wqkvc, CD, nullptr, qkv, CQKV, bqkv, nullptr, 0, 16);

    // fused attention (wo/w1/w2 conversion overlaps with this)
    dim3 gA(CS / 128, CB * CH);
    flash_kernel<<<gA, 256, SMFL>>>(qkv, mask, oh);

    // join 2: remaining weights ready
    cudaStreamWaitEvent(0, eW2, 0);

    // x1 = O wo^T + bo + x -> out (fp32)
    mm_gemm<64,128><<<dim3(CD / 128, NTOK / 64), 128, SMSML>>>(
        oh, CD, woc, CD, out, nullptr, CD, bo, x, 0, 16);

    // LN2 -> xn (fp16)
    ln_kernel<<<NTOK / 8, 256>>>(out, g2, be2, xnh);

    // h1 = gelu(xn w1^T + b1) (fp16)
    mm_gemm<128,256><<<dim3(CDFF / 256, NTOK / 128), 512, SMBIG>>>(
        xnh, CD, w1c, CD, nullptr, h1h, CDFF, b1, nullptr, 1, 16);

    // out = x1 + h1 w2^T + b2
    mm_gemm<64,128><<<dim3(CD / 128, NTOK / 64), 128, SMSML>>>(
        h1h, CDFF, w2c, CDFF, out, nullptr, CD, b2, out, 0, 64);
}

// round 16
// speedup vs baseline: 1.0647x; 1.0492x over previous
#include <cuda_runtime.h>
#include <cuda_fp16.h>
#include <math.h>
#include <stdint.h>

#define CB 8
#define CS 1024
#define CD 1024
#define CH 16
#define CDK 64
#define CDFF 4096
#define NTOK (CB*CS)
#define CQKV 3072
#define HTOK (NTOK/2)
typedef __half hf;

#define SWZ(o) ((o) ^ (((o) >> 3) & 0x70))
#define CP16(dst, src) asm volatile("cp.async.cg.shared.global [%0], [%1], 16;" :: "r"(dst), "l"(src) : "memory")

#define LDSM4(r, a) \
    asm volatile("ldmatrix.sync.aligned.m8n8.x4.shared.b16 {%0,%1,%2,%3}, [%4];" \
        : "=r"((r)[0]), "=r"((r)[1]), "=r"((r)[2]), "=r"((r)[3]) : "r"(a))
#define LDSM4T(r, a) \
    asm volatile("ldmatrix.sync.aligned.m8n8.x4.trans.shared.b16 {%0,%1,%2,%3}, [%4];" \
        : "=r"((r)[0]), "=r"((r)[1]), "=r"((r)[2]), "=r"((r)[3]) : "r"(a))

#define MMA(c, a, b) \
    asm volatile("mma.sync.aligned.m16n8k16.row.col.f32.f16.f16.f32 " \
        "{%0,%1,%2,%3},{%4,%5,%6,%7},{%8,%9},{%0,%1,%2,%3};" \
        : "+f"((c)[0]), "+f"((c)[1]), "+f"((c)[2]), "+f"((c)[3]) \
        : "r"((a)[0]), "r"((a)[1]), "r"((a)[2]), "r"((a)[3]), "r"((b)[0]), "r"((b)[1]))

__device__ __forceinline__ float gelu_f(float x) {
    float x3 = x * x * x;
    return 0.5f * x * (1.0f + tanhf(0.7978845608028654f * (x + 0.044715f * x3)));
}

// ------------------------- scratch -------------------------
__device__ hf g_xnh[NTOK*CD];
__device__ hf g_qkv[(size_t)NTOK*CQKV];          // [B,S, (Q|K|V) x H*DK]
__device__ hf g_oh[NTOK*CD];
__device__ hf g_h1h[(size_t)NTOK*CDFF];
__device__ hf g_wqkv[(size_t)CQKV*CD];           // rows: wq*0.125 | wk | wv
__device__ float g_bqkv[CQKV];
__device__ hf g_wo[CD*CD];
__device__ hf g_w1[(size_t)CDFF*CD], g_w2[(size_t)CD*CDFF];

__global__ __launch_bounds__(256)
void conv_kernel(const float* __restrict__ w, hf* __restrict__ h, int n4, float scale) {
    int i = blockIdx.x * 256 + threadIdx.x;
    if (i < n4) {
        float4 v = reinterpret_cast<const float4*>(w)[i];
        reinterpret_cast<__half2*>(h)[2*i]   = __floats2half2_rn(v.x * scale, v.y * scale);
        reinterpret_cast<__half2*>(h)[2*i+1] = __floats2half2_rn(v.z * scale, v.w * scale);
    }
}

__global__ __launch_bounds__(256)
void bias_pack_kernel(const float* __restrict__ bq, const float* __restrict__ bk,
                      const float* __restrict__ bv, float* __restrict__ o) {
    int i = blockIdx.x * 256 + threadIdx.x;
    if (i < CD)            o[i] = bq[i] * 0.125f;
    else if (i < 2 * CD)   o[i] = bk[i - CD];
    else if (i < 3 * CD)   o[i] = bv[i - 2 * CD];
}

// ------------------------- LayerNorm: warp-per-row, barrier-free -------------------------
__global__ __launch_bounds__(256)
void ln_kernel(const float* __restrict__ x, const float* __restrict__ gamma,
               const float* __restrict__ beta, hf* __restrict__ oh) {
    const int row = blockIdx.x * 8 + (threadIdx.x >> 5);
    const int lane = threadIdx.x & 31;
    const float4* xr = reinterpret_cast<const float4*>(x + (size_t)row * CD);
    float4 v[8];
#pragma unroll
    for (int i = 0; i < 8; i++) v[i] = xr[lane + 32 * i];

    float s = 0.f;
#pragma unroll
    for (int i = 0; i < 8; i++) s += (v[i].x + v[i].y) + (v[i].z + v[i].w);
#pragma unroll
    for (int o = 16; o > 0; o >>= 1) s += __shfl_xor_sync(~0u, s, o);
    const float mean = s * (1.0f / CD);

    float q = 0.f;
#pragma unroll
    for (int i = 0; i < 8; i++) {
        float a = v[i].x - mean, b = v[i].y - mean;
        float c = v[i].z - mean, d = v[i].w - mean;
        q += (a * a + b * b) + (c * c + d * d);
    }
#pragma unroll
    for (int o = 16; o > 0; o >>= 1) q += __shfl_xor_sync(~0u, q, o);
    const float rstd = 1.0f / (sqrtf(q * (1.0f / (CD - 1))) + 1e-5f);

    const float4* gr = reinterpret_cast<const float4*>(gamma);
    const float4* br = reinterpret_cast<const float4*>(beta);
    hf* orow = oh + (size_t)row * CD;
#pragma unroll
    for (int i = 0; i < 8; i++) {
        float4 g = gr[lane + 32 * i], bb = br[lane + 32 * i];
        __half2 h0 = __floats2half2_rn(g.x * (v[i].x - mean) * rstd + bb.x,
                                       g.y * (v[i].y - mean) * rstd + bb.y);
        __half2 h1 = __floats2half2_rn(g.z * (v[i].z - mean) * rstd + bb.z,
                                       g.w * (v[i].w - mean) * rstd + bb.w);
        uint2 u;
        u.x = *reinterpret_cast<uint32_t*>(&h0);
        u.y = *reinterpret_cast<uint32_t*>(&h1);
        *reinterpret_cast<uint2*>(orow + (lane + 32 * i) * 4) = u;
    }
}

// ---------------------------------------------------------------------------
// Flash attention: O = softmax(mask(Q K^T)) V with Q pre-scaled by 0.125.
// Pointers may be pre-offset by a batch-half; b local to the launch.
// ---------------------------------------------------------------------------
__global__ __launch_bounds__(256)
void flash_kernel(const hf* __restrict__ QKV, const int* __restrict__ mask,
                  hf* __restrict__ Oh)
{
    extern __shared__ char smem[];
    const uint32_t sb = (uint32_t)__cvta_generic_to_shared(smem);
    const int tid = threadIdx.x, wid = tid >> 5, lane = tid & 31;
    const int qt = blockIdx.x, z = blockIdx.y;
    const int b = z >> 4, h = z & 15;
    const int qbase = qt * 128;
    const size_t headOff = (size_t)h * 64;

    auto gaddr = [&](int part, int srow, int cu) {
        return QKV + ((size_t)(b * CS + srow) * CQKV + part * CD + headOff + (cu << 3));
    };

#pragma unroll
    for (int i = 0; i < 4; i++) {
        int u = tid + i * 256, r = u >> 3, cu = u & 7;
        CP16(sb + SWZ(r * 128 + cu * 16), gaddr(0, qbase + r, cu));
    }

    auto loadKV = [&](int it, int s) {
        const uint32_t base = sb + 16384 + s * 32768;
        const int kb = it * 128;
#pragma unroll
        for (int i = 0; i < 4; i++) {
            int u = tid + i * 256, r = u >> 3, cu = u & 7;
            uint32_t sw = SWZ(r * 128 + cu * 16);
            CP16(base + sw,         gaddr(1, kb + r, cu));
            CP16(base + 16384 + sw, gaddr(2, kb + r, cu));
        }
    };

    loadKV(0, 0);
    asm volatile("cp.async.commit_group;" ::: "memory");
    loadKV(1, 1);
    asm volatile("cp.async.commit_group;" ::: "memory");

    float oacc[8][4];
#pragma unroll
    for (int i = 0; i < 8; i++)
#pragma unroll
        for (int j = 0; j < 4; j++) oacc[i][j] = 0.f;
    float m_old[2] = {-INFINITY, -INFINITY};
    float l_sum[2] = {0.f, 0.f};

    const int li = lane >> 3, lj = lane & 7;
    const int rbase = wid * 16 + (lane >> 2);

    for (int it = 0; it < 8; it++) {
        const int s = it & 1;
        if (it < 7) asm volatile("cp.async.wait_group 1;" ::: "memory");
        else        asm volatile("cp.async.wait_group 0;" ::: "memory");
        __syncthreads();

        const uint32_t kst = sb + 16384 + s * 32768;
        const uint32_t vst = kst + 16384;

        float sacc[16][4];
#pragma unroll
        for (int i = 0; i < 16; i++)
#pragma unroll
            for (int j = 0; j < 4; j++) sacc[i][j] = 0.f;

#pragma unroll
        for (int kk = 0; kk < 4; kk++) {
            uint32_t ah[4];
            uint32_t aoff = SWZ((wid * 16 + ((li & 1) << 3) + lj) * 128 + (kk * 16 + ((li >> 1) << 3)) * 2);
            LDSM4(ah, sb + aoff);
            uint32_t bh[8][4];
#pragma unroll
            for (int nt = 0; nt < 8; nt++) {
                uint32_t off = SWZ((nt * 16 + ((li >> 1) << 3) + lj) * 128 + (kk * 16 + ((li & 1) << 3)) * 2);
                LDSM4(bh[nt], kst + off);
            }
#pragma unroll
            for (int nt = 0; nt < 8; nt++) { MMA(sacc[2*nt], ah, bh[nt]); MMA(sacc[2*nt+1], ah, bh[nt]+2); }
        }

#pragma unroll
        for (int rr = 0; rr < 2; rr++) {
            const int grow = qbase + rbase + rr * 8;
            const int2* mrow = (const int2*)(mask + ((size_t)(b * CS + grow)) * CS + it * 128 + ((lane & 3) << 1));
            float mx = -INFINITY;
#pragma unroll
            for (int ni = 0; ni < 16; ni++) {
                int2 mv = mrow[ni * 4];
                float v0 = mv.x ? sacc[ni][2*rr]   : -1e9f;
                float v1 = mv.y ? sacc[ni][2*rr+1] : -1e9f;
                sacc[ni][2*rr] = v0; sacc[ni][2*rr+1] = v1;
                mx = fmaxf(mx, fmaxf(v0, v1));
            }
            mx = fmaxf(mx, __shfl_xor_sync(~0u, mx, 1));
            mx = fmaxf(mx, __shfl_xor_sync(~0u, mx, 2));
            const float mnew = fmaxf(m_old[rr], mx);
            const float scl = __expf(m_old[rr] - mnew);
            float rsum = 0.f;
#pragma unroll
            for (int ni = 0; ni < 16; ni++) {
                float p0 = __expf(sacc[ni][2*rr]   - mnew);
                float p1 = __expf(sacc[ni][2*rr+1] - mnew);
                sacc[ni][2*rr] = p0; sacc[ni][2*rr+1] = p1;
                rsum += p0 + p1;
            }
            rsum += __shfl_xor_sync(~0u, rsum, 1);
            rsum += __shfl_xor_sync(~0u, rsum, 2);
            l_sum[rr] = l_sum[rr] * scl + rsum;
            m_old[rr] = mnew;
#pragma unroll
            for (int ni = 0; ni < 8; ni++) { oacc[ni][2*rr] *= scl; oacc[ni][2*rr+1] *= scl; }
        }

#pragma unroll
        for (int kk = 0; kk < 8; kk++) {
            uint32_t ah2[4];
            const int f0 = 2 * kk, f1 = 2 * kk + 1;
            {
                __half2 h0 = __floats2half2_rn(sacc[f0][0], sacc[f0][1]);
                __half2 h1 = __floats2half2_rn(sacc[f0][2], sacc[f0][3]);
                __half2 h2 = __floats2half2_rn(sacc[f1][0], sacc[f1][1]);
                __half2 h3 = __floats2half2_rn(sacc[f1][2], sacc[f1][3]);
                ah2[0] = *reinterpret_cast<uint32_t*>(&h0);
                ah2[1] = *reinterpret_cast<uint32_t*>(&h1);
                ah2[2] = *reinterpret_cast<uint32_t*>(&h2);
                ah2[3] = *reinterpret_cast<uint32_t*>(&h3);
            }
            uint32_t vf[4][4];
#pragma unroll
            for (int nb = 0; nb < 4; nb++) {
                uint32_t off = SWZ((kk * 16 + ((li & 1) << 3) + lj) * 128 + (nb * 16 + ((li >> 1) << 3)) * 2);
                LDSM4T(vf[nb], vst + off);
            }
#pragma unroll
            for (int nb = 0; nb < 4; nb++) { MMA(oacc[2*nb], ah2, vf[nb]); MMA(oacc[2*nb+1], ah2, vf[nb]+2); }
        }

        __syncthreads();
        if (it + 2 < 8) {
            loadKV(it + 2, s);
            asm volatile("cp.async.commit_group;" ::: "memory");
        }
    }

#pragma unroll
    for (int rr = 0; rr < 2; rr++) {
        const int grow = qbase + rbase + rr * 8;
        const float inv = 1.f / l_sum[rr];
        const size_t base = (size_t)(b * CS + grow) * CD + headOff + ((lane & 3) << 1);
#pragma unroll
        for (int ni = 0; ni < 8; ni++) {
            float v0 = oacc[ni][2*rr] * inv, v1 = oacc[ni][2*rr+1] * inv;
            *reinterpret_cast<__half2*>(&Oh[base + 8 * ni]) = __floats2half2_rn(v0, v1);
        }
    }
}

// ---------------------------------------------------------------------------
// mma.sync fp16 GEMM (1-pass, 3-stage pipeline): C[BM x BN] = A . B^T, K=NC*64.
// ---------------------------------------------------------------------------
template<int BM, int BN>
__global__ __launch_bounds__((BM/32)*(BN/64)*32)
void mm_gemm(const hf* __restrict__ Ah, int lda,
             const hf* __restrict__ Bh, int ldb,
             float* __restrict__ outf, hf* __restrict__ outh, int ldc,
             const float* __restrict__ bias, const float* __restrict__ res,
             int gelu, int NC)
{
    constexpr int WMC = BM / 32;
    constexpr int WNC = BN / 64;
    constexpr int THREADS = WMC * WNC * 32;
    constexpr int NF  = 8;
    constexpr int ASZ = BM * 128;
    constexpr int BSZ = BN * 128;
    constexpr int STG = ASZ + BSZ;

    extern __shared__ char smem[];
    const uint32_t sb = (uint32_t)__cvta_generic_to_shared(smem);
    const int tid = threadIdx.x, wid = tid >> 5, lane = tid & 31;
    const int bm = blockIdx.y * BM, bn = blockIdx.x * BN;

    const int wm = (wid % WMC) * 32;
    const int wn = (wid / WMC) * 64;

    auto load_chunk = [&](int c, int s) {
        const uint32_t base = sb + s * STG;
        const int k0 = c * 64;
#pragma unroll
        for (int i = 0; i < BM * 8 / THREADS; i++) {
            int u = tid + i * THREADS, r = u >> 3, cu = u & 7;
            CP16(base + SWZ(r * 128 + cu * 16), Ah + (size_t)(bm + r) * lda + k0 + cu * 8);
        }
#pragma unroll
        for (int i = 0; i < BN * 8 / THREADS; i++) {
            int u = tid + i * THREADS, r = u >> 3, cu = u & 7;
            CP16(base + ASZ + SWZ(r * 128 + cu * 16), Bh + (size_t)(bn + r) * ldb + k0 + cu * 8);
        }
    };

    float acc[2][NF][4];
#pragma unroll
    for (int mi = 0; mi < 2; mi++)
#pragma unroll
        for (int ni = 0; ni < NF; ni++)
#pragma unroll
            for (int cc = 0; cc < 4; cc++) acc[mi][ni][cc] = 0.f;

    load_chunk(0, 0);
    asm volatile("cp.async.commit_group;" ::: "memory");
    load_chunk(1, 1);
    asm volatile("cp.async.commit_group;" ::: "memory");

    const int li = lane >> 3, lj = lane & 7;

    for (int c = 0; c < NC; c++) {
        if (c + 2 < NC) {
            load_chunk(c + 2, (c + 2) % 3);
            asm volatile("cp.async.commit_group;" ::: "memory");
            asm volatile("cp.async.wait_group 2;" ::: "memory");
        } else if (c + 1 < NC) {
            asm volatile("cp.async.wait_group 1;" ::: "memory");
        } else {
            asm volatile("cp.async.wait_group 0;" ::: "memory");
        }
        __syncthreads();

        const uint32_t aBase = sb + (c % 3) * STG;
        const uint32_t bBase = aBase + ASZ;

#pragma unroll
        for (int ks = 0; ks < 4; ks++) {
            const int kb = ks * 16;
            uint32_t ah[2][4];
#pragma unroll
            for (int mi = 0; mi < 2; mi++) {
                int row = wm + mi * 16 + ((li & 1) << 3) + lj;
                int col = kb + ((li >> 1) << 3);
                LDSM4(ah[mi], aBase + SWZ(row * 128 + col * 2));
            }
            uint32_t bh[NF][2];
#pragma unroll
            for (int nt = 0; nt < NF / 2; nt++) {
                int row = wn + nt * 16 + ((li >> 1) << 3) + lj;
                int col = kb + ((li & 1) << 3);
                uint32_t r4[4];
                LDSM4(r4, bBase + SWZ(row * 128 + col * 2));
                bh[2*nt][0] = r4[0]; bh[2*nt][1] = r4[1];
                bh[2*nt+1][0] = r4[2]; bh[2*nt+1][1] = r4[3];
            }
#pragma unroll
            for (int mi = 0; mi < 2; mi++)
#pragma unroll
                for (int ni = 0; ni < NF; ni++) MMA(acc[mi][ni], ah[mi], bh[ni]);
        }
        __syncthreads();
    }

#pragma unroll
    for (int mi = 0; mi < 2; mi++) {
#pragma unroll
        for (int ni = 0; ni < NF; ni++) {
            const int m0 = bm + wm + mi * 16 + (lane >> 2);
            const int n0 = bn + wn + ni * 8 + ((lane & 3) << 1);
#pragma unroll
            for (int rr = 0; rr < 2; rr++) {
                const int m = m0 + rr * 8;
                float v0 = acc[mi][ni][2*rr + 0];
                float v1 = acc[mi][ni][2*rr + 1];
                if (bias) { v0 += bias[n0]; v1 += bias[n0 + 1]; }
                if (gelu) { v0 = gelu_f(v0); v1 = gelu_f(v1); }
                size_t idx = (size_t)m * ldc + n0;
                if (res) { v0 += res[idx]; v1 += res[idx + 1]; }
                if (outf) {
                    outf[idx] = v0; outf[idx + 1] = v1;
                } else {
                    *reinterpret_cast<__half2*>(&outh[idx]) = __floats2half2_rn(v0, v1);
                }
            }
        }
    }
}

// ---------------------------------------------------------------------------
extern "C" void kernel_launch(void* const* d_in, const int* in_sizes, int n_in,
                              void* d_out, int out_size)
{
    const float* x    = (const float*)d_in[0];
    const int*   mask = (const int*)  d_in[1];
    const float* wq = (const float*)d_in[2],  *bq = (const float*)d_in[3];
    const float* wk = (const float*)d_in[4],  *bk = (const float*)d_in[5];
    const float* wv = (const float*)d_in[6],  *bv = (const float*)d_in[7];
    const float* wo = (const float*)d_in[8],  *bo = (const float*)d_in[9];
    const float* w1 = (const float*)d_in[10], *b1 = (const float*)d_in[11];
    const float* w2 = (const float*)d_in[12], *b2 = (const float*)d_in[13];
    const float* g1 = (const float*)d_in[14], *be1 = (const float*)d_in[15];
    const float* g2 = (const float*)d_in[16], *be2 = (const float*)d_in[17];
    float* out = (float*)d_out;

    hf *xnh,*qkv,*oh,*h1h,*wqkvc,*woc,*w1c,*w2c;
    float *bqkv;
    cudaGetSymbolAddress((void**)&xnh, g_xnh);
    cudaGetSymbolAddress((void**)&qkv, g_qkv);
    cudaGetSymbolAddress((void**)&oh, g_oh);
    cudaGetSymbolAddress((void**)&h1h, g_h1h);
    cudaGetSymbolAddress((void**)&wqkvc, g_wqkv);
    cudaGetSymbolAddress((void**)&bqkv, g_bqkv);
    cudaGetSymbolAddress((void**)&woc, g_wo);
    cudaGetSymbolAddress((void**)&w1c, g_w1);
    cudaGetSymbolAddress((void**)&w2c, g_w2);

    const int SMBIG = 3 * (128 + 256) * 128;     // 147456
    const int SMSML = 3 * (64 + 128) * 128;      // 73728
    const int SMFL  = 16384 + 2 * 32768;         // 81920
    cudaFuncSetAttribute((const void*)mm_gemm<128,256>, cudaFuncAttributeMaxDynamicSharedMemorySize, SMBIG);
    cudaFuncSetAttribute((const void*)mm_gemm<64,128>,  cudaFuncAttributeMaxDynamicSharedMemorySize, SMSML);
    cudaFuncSetAttribute((const void*)flash_kernel, cudaFuncAttributeMaxDynamicSharedMemorySize, SMFL);

    // Streams/events created fresh each call AND destroyed before returning
    // (side streams are fully joined back into the capture stream first).
    cudaStream_t s1, s2;
    cudaEvent_t eF, eW1, eW2, eD;
    cudaStreamCreateWithFlags(&s1, cudaStreamNonBlocking);
    cudaStreamCreateWithFlags(&s2, cudaStreamNonBlocking);
    cudaEventCreateWithFlags(&eF,  cudaEventDisableTiming);
    cudaEventCreateWithFlags(&eW1, cudaEventDisableTiming);
    cudaEventCreateWithFlags(&eW2, cudaEventDisableTiming);
    cudaEventCreateWithFlags(&eD,  cudaEventDisableTiming);

    // fork
    cudaEventRecord(eF, 0);
    cudaStreamWaitEvent(s1, eF, 0);
    cudaStreamWaitEvent(s2, eF, 0);

    // s1: weight packing (QKV first, then wo/w1/w2)
    conv_kernel<<<1024, 256, 0, s1>>>(wq, wqkvc,               CD * CD / 4, 0.125f);
    conv_kernel<<<1024, 256, 0, s1>>>(wk, wqkvc + CD * CD,     CD * CD / 4, 1.0f);
    conv_kernel<<<1024, 256, 0, s1>>>(wv, wqkvc + 2 * CD * CD, CD * CD / 4, 1.0f);
    bias_pack_kernel<<<12, 256, 0, s1>>>(bq, bk, bv, bqkv);
    cudaEventRecord(eW1, s1);
    conv_kernel<<<1024, 256, 0, s1>>>(wo, woc, CD * CD / 4, 1.0f);
    conv_kernel<<<4096, 256, 0, s1>>>(w1, w1c, CDFF * CD / 4, 1.0f);
    conv_kernel<<<4096, 256, 0, s1>>>(w2, w2c, CD * CDFF / 4, 1.0f);
    cudaEventRecord(eW2, s1);

    // Per-half pointer offsets (batches 0-3 on stream 0, batches 4-7 on s2)
    const size_t oT = (size_t)HTOK * CD;
    const size_t oQ = (size_t)HTOK * CQKV;
    const size_t oH = (size_t)HTOK * CDFF;
    const size_t oM = (size_t)4 * CS * CS;

    dim3 gQKV(CQKV / 256, HTOK / 128);
    dim3 gA(CS / 128, 4 * CH);
    dim3 gO(CD / 128, HTOK / 64);
    dim3 gF1(CDFF / 256, HTOK / 128);

    // ---------------- half 0 (stream 0) ----------------
    ln_kernel<<<HTOK / 8, 256>>>(x, g1, be1, xnh);
    cudaStreamWaitEvent(0, eW1, 0);
    mm_gemm<128,256><<<gQKV, 512, SMBIG>>>(
        xnh, CD, wqkvc, CD, nullptr, qkv, CQKV, bqkv, nullptr, 0, 16);
    flash_kernel<<<gA, 256, SMFL>>>(qkv, mask, oh);
    cudaStreamWaitEvent(0, eW2, 0);
    mm_gemm<64,128><<<gO, 128, SMSML>>>(
        oh, CD, woc, CD, out, nullptr, CD, bo, x, 0, 16);
    ln_kernel<<<HTOK / 8, 256>>>(out, g2, be2, xnh);
    mm_gemm<128,256><<<gF1, 512, SMBIG>>>(
        xnh, CD, w1c, CD, nullptr, h1h, CDFF, b1, nullptr, 1, 16);
    mm_gemm<64,128><<<gO, 128, SMSML>>>(
        h1h, CDFF, w2c, CDFF, out, nullptr, CD, b2, out, 0, 64);

    // ---------------- half 1 (stream s2) ----------------
    ln_kernel<<<HTOK / 8, 256, 0, s2>>>(x + oT, g1, be1, xnh + oT);
    cudaStreamWaitEvent(s2, eW1, 0);
    mm_gemm<128,256><<<gQKV, 512, SMBIG, s2>>>(
        xnh + oT, CD, wqkvc, CD, nullptr, qkv + oQ, CQKV, bqkv, nullptr, 0, 16);
    flash_kernel<<<gA, 256, SMFL, s2>>>(qkv + oQ, mask + oM, oh + oT);
    cudaStreamWaitEvent(s2, eW2, 0);
    mm_gemm<64,128><<<gO, 128, SMSML, s2>>>(
        oh + oT, CD, woc, CD, out + oT, nullptr, CD, bo, x + oT, 0, 16);
    ln_kernel<<<HTOK / 8, 256, 0, s2>>>(out + oT, g2, be2, xnh + oT);
    mm_gemm<128,256><<<gF1, 512, SMBIG, s2>>>(
        xnh + oT, CD, w1c, CD, nullptr, h1h + oH, CDFF, b1, nullptr, 1, 16);
    mm_gemm<64,128><<<gO, 128, SMSML, s2>>>(
        h1h + oH, CDFF, w2c, CDFF, out + oT, nullptr, CD, b2, out + oT, 0, 64);
    cudaEventRecord(eD, s2);

    // join, then release all transient objects (side streams fully joined)
    cudaStreamWaitEvent(0, eD, 0);
    cudaStreamDestroy(s1);
    cudaStreamDestroy(s2);
    cudaEventDestroy(eF);
    cudaEventDestroy(eW1);
    cudaEventDestroy(eW2);
    cudaEventDestroy(eD);
}